// round 4
// baseline (speedup 1.0000x reference)
#include <cuda_runtime.h>
#include <cuda_bf16.h>
#include <math.h>

#define B_  64
#define T_  1024
#define D_  32
#define G_  128
#define VOCAB_ 10000

// ---- static scratch (no allocations allowed) ----
__device__ float g_xg[B_ * T_ * G_];     // 33.5 MB : x@k + b, per (b,t,gate)
__device__ float g_h [B_ * T_ * D_];     //  8.4 MB : LSTM hidden states
__device__ float g_yp[B_ * 4 * 1024];    //  1.0 MB : per-(b,tile) partial y[32][32]

// ---- helpers ----
__device__ __forceinline__ float sigmoid_fast(float x) {
    float e = __expf(-x);
    float r;
    asm("rcp.approx.f32 %0, %1;" : "=f"(r) : "f"(1.0f + e));
    return r;
}
__device__ __forceinline__ unsigned long long pk(float a, float b) {
    unsigned long long r;
    asm("mov.b64 %0, {%1, %2};" : "=l"(r) : "f"(a), "f"(b));
    return r;
}
__device__ __forceinline__ void upk(unsigned long long v, float& a, float& b) {
    asm("mov.b64 {%0, %1}, %2;" : "=f"(a), "=f"(b) : "l"(v));
}
__device__ __forceinline__ unsigned long long ffma2(unsigned long long a,
                                                    unsigned long long b,
                                                    unsigned long long c) {
    unsigned long long r;
    asm("fma.rn.f32x2 %0, %1, %2, %3;" : "=l"(r) : "l"(a), "l"(b), "l"(c));
    return r;
}

// ============================================================
// Kernel 1: zero-token index queue (last 100 zeros, ascending, -1 padded front)
// ============================================================
__global__ void queue_kernel(const int* __restrict__ in, float* __restrict__ out,
                             int out_size) {
    if (out_size < 2248) return;
    float* q = out + (out_size - 200);
    int tid = threadIdx.x;                 // 0..1023
    int base = tid * 64;
    int cnt = 0;
#pragma unroll 8
    for (int k = 0; k < 64; k++) {
        int u = in[base + k];
        int id = (u < VOCAB_) ? u : 0;
        if (id == 0) cnt++;
    }
    int lane = tid & 31, wid = tid >> 5;
    // warp inclusive scan
    int v = cnt;
#pragma unroll
    for (int o = 1; o < 32; o <<= 1) {
        int t = __shfl_up_sync(0xffffffffu, v, o);
        if (lane >= o) v += t;
    }
    __shared__ int wsum[32];
    __shared__ int woff[32];
    __shared__ int stot;
    if (lane == 31) wsum[wid] = v;
    __syncthreads();
    if (wid == 0) {
        int x = wsum[lane];
        int y = x;
#pragma unroll
        for (int o = 1; o < 32; o <<= 1) {
            int t = __shfl_up_sync(0xffffffffu, y, o);
            if (lane >= o) y += t;
        }
        woff[lane] = y - x;
        if (lane == 31) stot = y;
    }
    __syncthreads();
    int total = stot;
    int excl = woff[wid] + v - cnt;
    if (tid < 200) q[tid] = -1.0f;
    __syncthreads();
    int r = excl;
    for (int k = 0; k < 64; k++) {
        int p = base + k;
        int u = in[p];
        int id = (u < VOCAB_) ? u : 0;
        if (id == 0) {
            int slot = r - total + 100;   // keep last 100, ascending at tail
            if (slot >= 0) {
                q[slot * 2]     = (float)(p >> 10);
                q[slot * 2 + 1] = (float)(p & 1023);
            }
            r++;
        }
    }
}

// ============================================================
// Kernel 2: xg[b,t,g] = b_lstm[g] + sum_d emb[id(b,t)][d] * k[d][g]
// grid 512 (= 64 b * 8 tchunks), 256 threads; k column held in registers
// ============================================================
__global__ __launch_bounds__(256) void xg_kernel(const int* __restrict__ inp,
                                                 const float* __restrict__ emb,
                                                 const float* __restrict__ klstm,
                                                 const float* __restrict__ blstm) {
    int b  = blockIdx.x >> 3;
    int tb = (blockIdx.x & 7) * 128;
    int tid = threadIdx.x, lane = tid & 31, w = tid >> 5;
    float kr[4][32];
#pragma unroll
    for (int d = 0; d < 32; d++)
#pragma unroll
        for (int qq = 0; qq < 4; qq++) kr[qq][d] = klstm[d * 128 + qq * 32 + lane];
    float br[4];
#pragma unroll
    for (int qq = 0; qq < 4; qq++) br[qq] = blstm[qq * 32 + lane];

    for (int i = 0; i < 16; i++) {
        int t = tb + w * 16 + i;
        int u = inp[b * T_ + t];
        int id = (u < VOCAB_) ? u : 0;
        float ev = emb[id * 32 + lane];
        float a0 = br[0], a1 = br[1], a2 = br[2], a3 = br[3];
#pragma unroll
        for (int d = 0; d < 32; d++) {
            float e = __shfl_sync(0xffffffffu, ev, d);
            a0 = fmaf(e, kr[0][d], a0);
            a1 = fmaf(e, kr[1][d], a1);
            a2 = fmaf(e, kr[2][d], a2);
            a3 = fmaf(e, kr[3][d], a3);
        }
        float* o = g_xg + (b * T_ + t) * G_;
        o[lane] = a0; o[32 + lane] = a1; o[64 + lane] = a2; o[96 + lane] = a3;
    }
}

// ============================================================
// Kernel 3: LSTM recurrence. 64 blocks (1 per batch) x 128 threads.
// thread g owns gate output g (gate = g>>5: i,f,g,o; unit = g&31).
// rk column in registers; h replicated per warp, broadcast via shfl.
// ONE __syncthreads per step (double-buffered zact).
// ============================================================
__global__ __launch_bounds__(128, 1) void lstm_kernel(const float* __restrict__ rk) {
    int b = blockIdx.x;
    int g = threadIdx.x;
    int lane = g & 31, w = g >> 5;
    float rkreg[32];
#pragma unroll
    for (int d = 0; d < 32; d++) rkreg[d] = rk[d * 128 + g];
    __shared__ float zact[2][128];
    float h = 0.f, c = 0.f;
    const float* xgb = g_xg + b * T_ * G_;
    float* hb = g_h + b * T_ * D_;
    float xcur = xgb[g];
    for (int t = 0; t < T_; t++) {
        float z = xcur;
        if (t < T_ - 1) xcur = xgb[(t + 1) * G_ + g];   // prefetch next step
        float z0 = 0.f, z1 = 0.f, z2 = 0.f, z3 = 0.f;
#pragma unroll
        for (int d = 0; d < 32; d += 4) {
            z0 = fmaf(__shfl_sync(0xffffffffu, h, d + 0), rkreg[d + 0], z0);
            z1 = fmaf(__shfl_sync(0xffffffffu, h, d + 1), rkreg[d + 1], z1);
            z2 = fmaf(__shfl_sync(0xffffffffu, h, d + 2), rkreg[d + 2], z2);
            z3 = fmaf(__shfl_sync(0xffffffffu, h, d + 3), rkreg[d + 3], z3);
        }
        z += (z0 + z1) + (z2 + z3);
        float a = (w == 2) ? tanhf(z) : sigmoid_fast(z);
        zact[t & 1][g] = a;
        __syncthreads();
        float ai = zact[t & 1][lane];
        float af = zact[t & 1][32 + lane];
        float ag = zact[t & 1][64 + lane];
        float ao = zact[t & 1][96 + lane];
        c = fmaf(af, c, ai * ag);
        h = ao * tanhf(c);
        if (w == 0) hb[t * 32 + lane] = h;
    }
}

// ============================================================
// Kernel 4: fused attention + ctx + partial y. grid (4 tiles, 64 b), 256 thr.
// lane = query row (warp owns 32 rows); s-loop broadcasts h_s from smem.
// All FMAs are packed f32x2 (FFMA-3reg is half-rate on sm_103a).
// ============================================================
#define ATTN_SMEM ((32768 + 256 * 33) * 4)
__global__ __launch_bounds__(256, 1) void attn_kernel() {
    extern __shared__ float sm[];
    float* hs   = sm;            // [1024][32]
    float* ctxs = sm + 32768;    // [256][33] (padded)
    int b = blockIdx.y, tile = blockIdx.x;
    int tid = threadIdx.x, lane = tid & 31, w = tid >> 5;
    const float* hb = g_h + b * (T_ * D_);
    {   // load full h[b] into smem (natural [s][32] layout, float4)
        const float4* src = (const float4*)hb;
        float4* dst = (float4*)hs;
        for (int i = tid; i < 8192; i += 256) dst[i] = src[i];
    }
    __syncthreads();
    int row = tile * 256 + w * 32 + lane;
    unsigned long long ht2[16];
    {
        const float4* hr = (const float4*)(hs + row * 32);
#pragma unroll
        for (int j = 0; j < 8; j++) {
            float4 a = hr[j];
            ht2[2 * j]     = pk(a.x, a.y);
            ht2[2 * j + 1] = pk(a.z, a.w);
        }
    }
    unsigned long long z64 = pk(0.f, 0.f);
    unsigned long long acc2[16];
#pragma unroll
    for (int k = 0; k < 16; k++) acc2[k] = z64;
    float Z = 0.f;

    for (int s = 0; s < T_; s++) {
        const float4* hr = (const float4*)(hs + s * 32);   // uniform addr -> broadcast
        unsigned long long hp[16];
#pragma unroll
        for (int j = 0; j < 8; j++) {
            float4 a = hr[j];
            hp[2 * j]     = pk(a.x, a.y);
            hp[2 * j + 1] = pk(a.z, a.w);
        }
        unsigned long long d0 = ffma2(hp[0], ht2[0], z64);
        unsigned long long d1 = ffma2(hp[1], ht2[1], z64);
#pragma unroll
        for (int k = 2; k < 16; k += 2) {
            d0 = ffma2(hp[k],     ht2[k],     d0);
            d1 = ffma2(hp[k + 1], ht2[k + 1], d1);
        }
        float x0, x1, y0, y1;
        upk(d0, x0, x1);
        upk(d1, y0, y1);
        float dot = (x0 + y0) + (x1 + y1);
        float p = __expf(dot);            // |dot| <= 32, no overflow
        Z += p;
        unsigned long long pp = pk(p, p);
#pragma unroll
        for (int k = 0; k < 16; k++) acc2[k] = ffma2(pp, hp[k], acc2[k]);
    }
    float inv = 1.0f / Z;
    int rt = w * 32 + lane;
#pragma unroll
    for (int k = 0; k < 16; k++) {
        float x, y;
        upk(acc2[k], x, y);
        ctxs[rt * 33 + 2 * k]     = x * inv;
        ctxs[rt * 33 + 2 * k + 1] = y * inv;
    }
    __syncthreads();
    // partial y[d][e] = sum over this tile's 256 rows of ctx[t][d]*h[t][e]
    float* yp = g_yp + (b * 4 + tile) * 1024;
    int tbase = tile * 256;
#pragma unroll
    for (int pi = 0; pi < 4; pi++) {
        int p = tid * 4 + pi;
        int d = p >> 5, e = p & 31;
        float sacc = 0.f;
        for (int t = 0; t < 256; t++)
            sacc = fmaf(ctxs[t * 33 + d], hs[(tbase + t) * 32 + e], sacc);
        yp[p] = sacc;
    }
}

// ============================================================
// Kernel 5: reduce tiles -> y[32][32]; out = sigmoid(relu(yW1+b1)W2+b2)
// ============================================================
__global__ __launch_bounds__(128) void final_kernel(const float* __restrict__ W1,
                                                    const float* __restrict__ b1,
                                                    const float* __restrict__ W2,
                                                    const float* __restrict__ b2,
                                                    float* __restrict__ out) {
    __shared__ float ysh[1024];
    int b = blockIdx.x, tid = threadIdx.x;
    const float* yp = g_yp + b * 4 * 1024;
    for (int i = tid; i < 1024; i += 128)
        ysh[i] = yp[i] + yp[1024 + i] + yp[2048 + i] + yp[3072 + i];
    __syncthreads();
    if (tid < 32) {
        int d = tid;
        float acc = b2[0];
        for (int e = 0; e < 32; e++) {
            float s = b1[e];
#pragma unroll
            for (int kk = 0; kk < 32; kk++)
                s = fmaf(ysh[d * 32 + kk], W1[kk * 32 + e], s);
            s = fmaxf(s, 0.f);
            acc = fmaf(s, W2[e], acc);
        }
        out[b * 32 + d] = 1.0f / (1.0f + __expf(-acc));
    }
}

// ============================================================
extern "C" void kernel_launch(void* const* d_in, const int* in_sizes, int n_in,
                              void* d_out, int out_size) {
    const int*   inputs = (const int*)  d_in[0];
    const float* emb    = (const float*)d_in[1];
    const float* klstm  = (const float*)d_in[2];
    const float* rklstm = (const float*)d_in[3];
    const float* blstm  = (const float*)d_in[4];
    const float* W1     = (const float*)d_in[5];
    const float* b1     = (const float*)d_in[6];
    const float* W2     = (const float*)d_in[7];
    const float* b2     = (const float*)d_in[8];
    float* out = (float*)d_out;

    cudaFuncSetAttribute(attn_kernel, cudaFuncAttributeMaxDynamicSharedMemorySize,
                         ATTN_SMEM);

    queue_kernel<<<1, 1024>>>(inputs, out, out_size);
    xg_kernel<<<512, 256>>>(inputs, emb, klstm, blstm);
    lstm_kernel<<<64, 128>>>(rklstm);
    attn_kernel<<<dim3(4, 64), 256, ATTN_SMEM>>>();
    final_kernel<<<64, 128>>>(W1, b1, W2, b2, out);
}

// round 5
// speedup vs baseline: 1.0901x; 1.0901x over previous
#include <cuda_runtime.h>
#include <cuda_bf16.h>
#include <math.h>

#define B_  64
#define T_  1024
#define D_  32
#define G_  128
#define VOCAB_ 10000

typedef unsigned long long ull;

// ---- static scratch (no allocations allowed) ----
__device__ ulonglong2 g_xg2[B_ * T_ * 32];   // 33.5 MB : packed (i,f),(g,o) xg pairs
__device__ float g_h [B_ * T_ * D_];         //  8.4 MB : LSTM hidden states
__device__ float g_yp[B_ * 2 * 1024];        //  0.5 MB : per-(b,tile) partial y[32][32]

// ---- helpers ----
__device__ __forceinline__ float sigmoid_fast(float x) {
    float e = __expf(-x);
    float r;
    asm("rcp.approx.f32 %0, %1;" : "=f"(r) : "f"(1.0f + e));
    return r;
}
__device__ __forceinline__ float tanh_fast(float x) {
    // tanh(x) = 1 - 2/(e^{2x}+1); handles +-inf limits correctly.
    float e = __expf(2.0f * x);
    float r;
    asm("rcp.approx.f32 %0, %1;" : "=f"(r) : "f"(e + 1.0f));
    return fmaf(-2.0f, r, 1.0f);
}
__device__ __forceinline__ ull pk(float a, float b) {
    ull r;
    asm("mov.b64 %0, {%1, %2};" : "=l"(r) : "f"(a), "f"(b));
    return r;
}
__device__ __forceinline__ void upk(ull v, float& a, float& b) {
    asm("mov.b64 {%0, %1}, %2;" : "=f"(a), "=f"(b) : "l"(v));
}
__device__ __forceinline__ ull ffma2(ull a, ull b, ull c) {
    ull r;
    asm("fma.rn.f32x2 %0, %1, %2, %3;" : "=l"(r) : "l"(a), "l"(b), "l"(c));
    return r;
}
__device__ __forceinline__ ull add2(ull a, ull b) {
    ull r;
    asm("add.rn.f32x2 %0, %1, %2;" : "=l"(r) : "l"(a), "l"(b));
    return r;
}

// ============================================================
// Kernel 1: zero-token index queue (last 100 zeros, ascending, -1 padded front)
// bitmask caches the zero predicate -> no reloads in pass 2.
// ============================================================
__global__ void queue_kernel(const int* __restrict__ in, float* __restrict__ out,
                             int out_size) {
    if (out_size < 2248) return;
    float* q = out + (out_size - 200);
    int tid = threadIdx.x;                 // 0..1023
    int base = tid * 64;
    ull m = 0;
    const int4* p4 = (const int4*)(in + base);
#pragma unroll
    for (int k = 0; k < 16; k++) {
        int4 v = p4[k];
        if (v.x == 0 || v.x >= VOCAB_) m |= 1ull << (4 * k + 0);
        if (v.y == 0 || v.y >= VOCAB_) m |= 1ull << (4 * k + 1);
        if (v.z == 0 || v.z >= VOCAB_) m |= 1ull << (4 * k + 2);
        if (v.w == 0 || v.w >= VOCAB_) m |= 1ull << (4 * k + 3);
    }
    int cnt = __popcll(m);
    int lane = tid & 31, wid = tid >> 5;
    int v = cnt;
#pragma unroll
    for (int o = 1; o < 32; o <<= 1) {
        int t = __shfl_up_sync(0xffffffffu, v, o);
        if (lane >= o) v += t;
    }
    __shared__ int wsum[32];
    __shared__ int woff[32];
    __shared__ int stot;
    if (lane == 31) wsum[wid] = v;
    __syncthreads();
    if (wid == 0) {
        int x = wsum[lane];
        int y = x;
#pragma unroll
        for (int o = 1; o < 32; o <<= 1) {
            int t = __shfl_up_sync(0xffffffffu, y, o);
            if (lane >= o) y += t;
        }
        woff[lane] = y - x;
        if (lane == 31) stot = y;
    }
    __syncthreads();
    int total = stot;
    int excl = woff[wid] + v - cnt;
    if (tid < 200) q[tid] = -1.0f;
    __syncthreads();
    int r = excl;
    ull mm = m;
    while (mm) {
        int k = __ffsll(mm) - 1;
        mm &= mm - 1;
        int slot = r - total + 100;
        if (slot >= 0) {
            int p = base + k;
            q[slot * 2]     = (float)(p >> 10);
            q[slot * 2 + 1] = (float)(p & 1023);
        }
        r++;
    }
}

// ============================================================
// Kernel 2: xg[b,t,*] = b_lstm + emb[id]@k, written as packed (i,f),(g,o) pairs
// ============================================================
__global__ __launch_bounds__(256) void xg_kernel(const int* __restrict__ inp,
                                                 const float* __restrict__ emb,
                                                 const float* __restrict__ klstm,
                                                 const float* __restrict__ blstm) {
    int b  = blockIdx.x >> 3;
    int tb = (blockIdx.x & 7) * 128;
    int tid = threadIdx.x, lane = tid & 31, w = tid >> 5;
    float kr[4][32];
#pragma unroll
    for (int d = 0; d < 32; d++)
#pragma unroll
        for (int qq = 0; qq < 4; qq++) kr[qq][d] = klstm[d * 128 + qq * 32 + lane];
    float br[4];
#pragma unroll
    for (int qq = 0; qq < 4; qq++) br[qq] = blstm[qq * 32 + lane];

    for (int i = 0; i < 16; i++) {
        int t = tb + w * 16 + i;
        int u = inp[b * T_ + t];
        int id = (u < VOCAB_) ? u : 0;
        float ev = emb[id * 32 + lane];
        float a0 = br[0], a1 = br[1], a2 = br[2], a3 = br[3];
#pragma unroll
        for (int d = 0; d < 32; d++) {
            float e = __shfl_sync(0xffffffffu, ev, d);
            a0 = fmaf(e, kr[0][d], a0);
            a1 = fmaf(e, kr[1][d], a1);
            a2 = fmaf(e, kr[2][d], a2);
            a3 = fmaf(e, kr[3][d], a3);
        }
        ulonglong2 vv;
        vv.x = pk(a0, a1);   // (i, f)
        vv.y = pk(a2, a3);   // (g, o)
        g_xg2[(b * T_ + t) * 32 + lane] = vv;
    }
}

// ============================================================
// Kernel 3: LSTM recurrence. 64 blocks x 1 warp (one batch per warp).
// Thread = unit; computes all 4 gates via packed f32x2 against register rk.
// h broadcast via 256B smem of duplicated pairs; ONE __syncwarp per step.
// ============================================================
__global__ __launch_bounds__(32, 1) void lstm_kernel(const float* __restrict__ rk) {
    int b = blockIdx.x;
    int lane = threadIdx.x;
    ull rkif[32], rkgo[32];
#pragma unroll
    for (int d = 0; d < 32; d++) {
        const float* rr = rk + d * 128;
        rkif[d] = pk(rr[lane],      rr[32 + lane]);
        rkgo[d] = pk(rr[64 + lane], rr[96 + lane]);
    }
    __shared__ ull h2[2][32];    // duplicated (h,h) pairs, double-buffered
    h2[0][lane] = pk(0.f, 0.f);
    float c = 0.f;
    float* hb = g_h + b * T_ * D_;
    const ulonglong2* xgb = g_xg2 + b * T_ * 32;
    ulonglong2 x0 = xgb[lane];
    ulonglong2 x1 = xgb[32 + lane];
    __syncwarp();
    const ull z64 = pk(0.f, 0.f);
    for (int t = 0; t < T_; t++) {
        ull zifa = x0.x, zgoa = x0.y;
        ull zifb = z64,  zgob = z64;
        x0 = x1;
        if (t + 2 < T_) x1 = xgb[(t + 2) * 32 + lane];   // prefetch distance 2
        const ulonglong2* hv = (const ulonglong2*)h2[t & 1];
#pragma unroll
        for (int j = 0; j < 16; j++) {
            ulonglong2 v = hv[j];                        // broadcast LDS.128
            zifa = ffma2(v.x, rkif[2 * j],     zifa);
            zgoa = ffma2(v.x, rkgo[2 * j],     zgoa);
            zifb = ffma2(v.y, rkif[2 * j + 1], zifb);
            zgob = ffma2(v.y, rkgo[2 * j + 1], zgob);
        }
        float zi, zf, zg, zo;
        upk(add2(zifa, zifb), zi, zf);
        upk(add2(zgoa, zgob), zg, zo);
        float ai = sigmoid_fast(zi);
        float af = sigmoid_fast(zf);
        float ao = sigmoid_fast(zo);
        float ag = tanh_fast(zg);
        c = fmaf(af, c, ai * ag);
        float h = ao * tanh_fast(c);
        hb[t * 32 + lane] = h;
        h2[(t & 1) ^ 1][lane] = pk(h, h);
        __syncwarp();
    }
}

// ============================================================
// Kernel 4: fused attention + ctx + partial y. grid (2 tiles, 64 b), 256 thr.
// Each thread owns TWO query rows (r0 = tile*512+tid, r1 = r0+256) sharing
// one hp load per s. All FMAs packed f32x2. 1 wave (128 blocks).
// ============================================================
#define ATTN_SMEM ((32768 + 512 * 33) * 4)
__global__ __launch_bounds__(256, 1) void attn_kernel() {
    extern __shared__ float sm[];
    float* hs   = sm;            // [1024][32]
    float* ctxs = sm + 32768;    // [512][33] (padded)
    int b = blockIdx.y, tile = blockIdx.x;
    int tid = threadIdx.x;
    const float* hb = g_h + b * (T_ * D_);
    {   // load full h[b] into smem
        const float4* src = (const float4*)hb;
        float4* dst = (float4*)hs;
        for (int i = tid; i < 8192; i += 256) dst[i] = src[i];
    }
    __syncthreads();
    int r0 = tile * 512 + tid;
    int r1 = r0 + 256;
    ull ht0[16], ht1[16];
    {
        const ulonglong2* a = (const ulonglong2*)(hs + r0 * 32);
        const ulonglong2* bptr = (const ulonglong2*)(hs + r1 * 32);
#pragma unroll
        for (int j = 0; j < 8; j++) {
            ulonglong2 u = a[j];    ht0[2 * j] = u.x; ht0[2 * j + 1] = u.y;
            ulonglong2 w = bptr[j]; ht1[2 * j] = w.x; ht1[2 * j + 1] = w.y;
        }
    }
    const ull z64 = pk(0.f, 0.f);
    ull acc0[16], acc1[16];
#pragma unroll
    for (int k = 0; k < 16; k++) { acc0[k] = z64; acc1[k] = z64; }
    float Z0 = 0.f, Z1 = 0.f;

    for (int s = 0; s < T_; s++) {
        const ulonglong2* hr = (const ulonglong2*)(hs + s * 32);  // uniform -> broadcast
        ull hp[16];
#pragma unroll
        for (int j = 0; j < 8; j++) {
            ulonglong2 v = hr[j];
            hp[2 * j] = v.x; hp[2 * j + 1] = v.y;
        }
        ull d0a = ffma2(hp[0], ht0[0], z64), d0b = ffma2(hp[1], ht0[1], z64);
        ull d1a = ffma2(hp[0], ht1[0], z64), d1b = ffma2(hp[1], ht1[1], z64);
#pragma unroll
        for (int k = 2; k < 16; k += 2) {
            d0a = ffma2(hp[k],     ht0[k],     d0a);
            d0b = ffma2(hp[k + 1], ht0[k + 1], d0b);
            d1a = ffma2(hp[k],     ht1[k],     d1a);
            d1b = ffma2(hp[k + 1], ht1[k + 1], d1b);
        }
        float a0, a1, b0, b1;
        upk(add2(d0a, d0b), a0, a1);
        float dot0 = a0 + a1;
        upk(add2(d1a, d1b), b0, b1);
        float dot1 = b0 + b1;
        float p0 = __expf(dot0);          // |dot| <= 32, no overflow
        float p1 = __expf(dot1);
        Z0 += p0; Z1 += p1;
        ull pp0 = pk(p0, p0), pp1 = pk(p1, p1);
#pragma unroll
        for (int k = 0; k < 16; k++) {
            acc0[k] = ffma2(pp0, hp[k], acc0[k]);
            acc1[k] = ffma2(pp1, hp[k], acc1[k]);
        }
    }
    float inv0 = 1.0f / Z0, inv1 = 1.0f / Z1;
#pragma unroll
    for (int k = 0; k < 16; k++) {
        float x, y;
        upk(acc0[k], x, y);
        ctxs[tid * 33 + 2 * k]     = x * inv0;
        ctxs[tid * 33 + 2 * k + 1] = y * inv0;
        upk(acc1[k], x, y);
        ctxs[(tid + 256) * 33 + 2 * k]     = x * inv1;
        ctxs[(tid + 256) * 33 + 2 * k + 1] = y * inv1;
    }
    __syncthreads();
    // partial y[d][e..e+3] = sum over this tile's 512 rows of ctx[t][d]*h[t][e..e+3]
    float* yp = g_yp + (b * 2 + tile) * 1024;
    int tbase = tile * 512;
    int p = tid * 4;
    int d = p >> 5, e = p & 31;
    float4 acc = make_float4(0.f, 0.f, 0.f, 0.f);
    for (int t = 0; t < 512; t++) {
        float cv = ctxs[t * 33 + d];
        float4 hv = *(const float4*)(hs + (tbase + t) * 32 + e);
        acc.x = fmaf(cv, hv.x, acc.x);
        acc.y = fmaf(cv, hv.y, acc.y);
        acc.z = fmaf(cv, hv.z, acc.z);
        acc.w = fmaf(cv, hv.w, acc.w);
    }
    *(float4*)(yp + p) = acc;
}

// ============================================================
// Kernel 5: reduce tiles -> y[32][32]; out = sigmoid(relu(yW1+b1)W2+b2)
// ============================================================
__global__ __launch_bounds__(128) void final_kernel(const float* __restrict__ W1,
                                                    const float* __restrict__ b1,
                                                    const float* __restrict__ W2,
                                                    const float* __restrict__ b2,
                                                    float* __restrict__ out) {
    __shared__ float ysh[1024];
    int b = blockIdx.x, tid = threadIdx.x;
    const float* yp = g_yp + b * 2 * 1024;
    for (int i = tid; i < 1024; i += 128)
        ysh[i] = yp[i] + yp[1024 + i];
    __syncthreads();
    if (tid < 32) {
        int d = tid;
        float acc = b2[0];
        for (int e = 0; e < 32; e++) {
            float s = b1[e];
#pragma unroll
            for (int kk = 0; kk < 32; kk++)
                s = fmaf(ysh[d * 32 + kk], W1[kk * 32 + e], s);
            s = fmaxf(s, 0.f);
            acc = fmaf(s, W2[e], acc);
        }
        out[b * 32 + d] = 1.0f / (1.0f + __expf(-acc));
    }
}

// ============================================================
extern "C" void kernel_launch(void* const* d_in, const int* in_sizes, int n_in,
                              void* d_out, int out_size) {
    const int*   inputs = (const int*)  d_in[0];
    const float* emb    = (const float*)d_in[1];
    const float* klstm  = (const float*)d_in[2];
    const float* rklstm = (const float*)d_in[3];
    const float* blstm  = (const float*)d_in[4];
    const float* W1     = (const float*)d_in[5];
    const float* b1     = (const float*)d_in[6];
    const float* W2     = (const float*)d_in[7];
    const float* b2     = (const float*)d_in[8];
    float* out = (float*)d_out;

    cudaFuncSetAttribute(attn_kernel, cudaFuncAttributeMaxDynamicSharedMemorySize,
                         ATTN_SMEM);

    queue_kernel<<<1, 1024>>>(inputs, out, out_size);
    xg_kernel<<<512, 256>>>(inputs, emb, klstm, blstm);
    lstm_kernel<<<64, 32>>>(rklstm);
    attn_kernel<<<dim3(2, 64), 256, ATTN_SMEM>>>();
    final_kernel<<<64, 128>>>(W1, b1, W2, b2, out);
}

// round 8
// speedup vs baseline: 1.1819x; 1.0842x over previous
#include <cuda_runtime.h>
#include <cuda_bf16.h>
#include <math.h>

#define B_  64
#define T_  1024
#define VOCAB_ 10000

typedef unsigned long long ull;

// ---- static scratch (no allocations allowed) ----
__device__ ulonglong2 g_xg2[B_ * T_ * 32];   // 33.5 MB : packed (i,f),(g,o), pre-scaled by log2e
__device__ float g_h [B_ * T_ * 32];         //  8.4 MB : LSTM hidden states
__device__ float g_pacc[B_ * 2 * T_ * 32];   // 16.8 MB : unnormalized ctx partials per s-chunk
__device__ float g_pz [B_ * 2 * T_];         //  0.5 MB : partial softmax sums per s-chunk

#define LOG2E 1.4426950408889634f

// ---- helpers ----
__device__ __forceinline__ float ex2f(float x) {
    float r; asm("ex2.approx.f32 %0, %1;" : "=f"(r) : "f"(x)); return r;
}
__device__ __forceinline__ float rcpf(float x) {
    float r; asm("rcp.approx.f32 %0, %1;" : "=f"(r) : "f"(x)); return r;
}
__device__ __forceinline__ ull pk(float a, float b) {
    ull r; asm("mov.b64 %0, {%1, %2};" : "=l"(r) : "f"(a), "f"(b)); return r;
}
__device__ __forceinline__ void upk(ull v, float& a, float& b) {
    asm("mov.b64 {%0, %1}, %2;" : "=f"(a), "=f"(b) : "l"(v));
}
__device__ __forceinline__ ull ffma2(ull a, ull b, ull c) {
    ull r; asm("fma.rn.f32x2 %0, %1, %2, %3;" : "=l"(r) : "l"(a), "l"(b), "l"(c)); return r;
}
__device__ __forceinline__ ull add2(ull a, ull b) {
    ull r; asm("add.rn.f32x2 %0, %1, %2;" : "=l"(r) : "l"(a), "l"(b)); return r;
}

// ============================================================
// Kernel 1: zero-token index queue (last 100 zeros, ascending, -1 padded front)
// ============================================================
__global__ void queue_kernel(const int* __restrict__ in, float* __restrict__ out,
                             int out_size) {
    if (out_size < 2248) return;
    float* q = out + (out_size - 200);
    int tid = threadIdx.x;                 // 0..1023
    int base = tid * 64;
    ull m = 0;
    const int4* p4 = (const int4*)(in + base);
#pragma unroll
    for (int k = 0; k < 16; k++) {
        int4 v = p4[k];
        if (v.x == 0 || v.x >= VOCAB_) m |= 1ull << (4 * k + 0);
        if (v.y == 0 || v.y >= VOCAB_) m |= 1ull << (4 * k + 1);
        if (v.z == 0 || v.z >= VOCAB_) m |= 1ull << (4 * k + 2);
        if (v.w == 0 || v.w >= VOCAB_) m |= 1ull << (4 * k + 3);
    }
    int cnt = __popcll(m);
    int lane = tid & 31, wid = tid >> 5;
    int v = cnt;
#pragma unroll
    for (int o = 1; o < 32; o <<= 1) {
        int t = __shfl_up_sync(0xffffffffu, v, o);
        if (lane >= o) v += t;
    }
    __shared__ int wsum[32];
    __shared__ int woff[32];
    __shared__ int stot;
    if (lane == 31) wsum[wid] = v;
    __syncthreads();
    if (wid == 0) {
        int x = wsum[lane];
        int y = x;
#pragma unroll
        for (int o = 1; o < 32; o <<= 1) {
            int t = __shfl_up_sync(0xffffffffu, y, o);
            if (lane >= o) y += t;
        }
        woff[lane] = y - x;
        if (lane == 31) stot = y;
    }
    __syncthreads();
    int total = stot;
    int excl = woff[wid] + v - cnt;
    if (tid < 200) q[tid] = -1.0f;
    __syncthreads();
    int r = excl;
    ull mm = m;
    while (mm) {
        int k = __ffsll(mm) - 1;
        mm &= mm - 1;
        int slot = r - total + 100;
        if (slot >= 0) {
            int p = base + k;
            q[slot * 2]     = (float)(p >> 10);
            q[slot * 2 + 1] = (float)(p & 1023);
        }
        r++;
    }
}

// ============================================================
// Kernel 2: xg = b_lstm + emb[id]@k, packed (i,f),(g,o), PRE-SCALED:
// i,f,o gates by -log2e (sigmoid via ex2), g gate by 2*log2e (tanh via ex2).
// ============================================================
__global__ __launch_bounds__(256) void xg_kernel(const int* __restrict__ inp,
                                                 const float* __restrict__ emb,
                                                 const float* __restrict__ klstm,
                                                 const float* __restrict__ blstm) {
    int b  = blockIdx.x >> 3;
    int tb = (blockIdx.x & 7) * 128;
    int tid = threadIdx.x, lane = tid & 31, w = tid >> 5;
    float kr[4][32];
#pragma unroll
    for (int d = 0; d < 32; d++)
#pragma unroll
        for (int qq = 0; qq < 4; qq++) kr[qq][d] = klstm[d * 128 + qq * 32 + lane];
    float br[4];
#pragma unroll
    for (int qq = 0; qq < 4; qq++) br[qq] = blstm[qq * 32 + lane];

    for (int i = 0; i < 16; i++) {
        int t = tb + w * 16 + i;
        int u = inp[b * T_ + t];
        int id = (u < VOCAB_) ? u : 0;
        float ev = emb[id * 32 + lane];
        float a0 = br[0], a1 = br[1], a2 = br[2], a3 = br[3];
#pragma unroll
        for (int d = 0; d < 32; d++) {
            float e = __shfl_sync(0xffffffffu, ev, d);
            a0 = fmaf(e, kr[0][d], a0);
            a1 = fmaf(e, kr[1][d], a1);
            a2 = fmaf(e, kr[2][d], a2);
            a3 = fmaf(e, kr[3][d], a3);
        }
        ulonglong2 vv;
        vv.x = pk(a0 * (-LOG2E), a1 * (-LOG2E));   // (i, f)  scaled for ex2-sigmoid
        vv.y = pk(a2 * (2.0f * LOG2E), a3 * (-LOG2E)); // (g, o)
        g_xg2[(b * T_ + t) * 32 + lane] = vv;
    }
}

// ============================================================
// Kernel 3: LSTM recurrence. 64 blocks x 1 warp. Thread = unit.
// (g,o) matvec first so its MUFUs overlap the (i,f) matvec issue.
// Prefetch ring depth 4. Activations: raw ex2.approx + rcp.approx.
// ============================================================
__global__ __launch_bounds__(32, 1) void lstm_kernel(const float* __restrict__ rk) {
    int b = blockIdx.x;
    int lane = threadIdx.x;
    ull rkif[32], rkgo[32];
#pragma unroll
    for (int d = 0; d < 32; d++) {
        const float* rr = rk + d * 128;
        rkif[d] = pk(rr[lane] * (-LOG2E),      rr[32 + lane] * (-LOG2E));
        rkgo[d] = pk(rr[64 + lane] * (2.0f * LOG2E), rr[96 + lane] * (-LOG2E));
    }
    __shared__ ull h2[2][32];
    h2[0][lane] = pk(0.f, 0.f);
    float c = 0.f;
    float* hb = g_h + b * T_ * 32;
    const ulonglong2* xgb = g_xg2 + b * T_ * 32;
    ulonglong2 xq0 = xgb[lane];
    ulonglong2 xq1 = xgb[32 + lane];
    ulonglong2 xq2 = xgb[64 + lane];
    ulonglong2 xq3 = xgb[96 + lane];
    __syncwarp();
    const ull z64 = pk(0.f, 0.f);

#define LSTM_STEP(XQ, TT)                                                     \
    {                                                                         \
        ull zgo1 = (XQ).y, zgo2 = z64, zif1 = (XQ).x, zif2 = z64;             \
        if ((TT) + 4 < T_) (XQ) = xgb[((TT) + 4) * 32 + lane];                \
        const ulonglong2* hv = (const ulonglong2*)h2[(TT) & 1];               \
        _Pragma("unroll")                                                     \
        for (int j = 0; j < 16; j++) {                                        \
            ulonglong2 vv = hv[j];                                            \
            zgo1 = ffma2(vv.x, rkgo[2 * j],     zgo1);                        \
            zgo2 = ffma2(vv.y, rkgo[2 * j + 1], zgo2);                        \
        }                                                                     \
        float zg, zo;                                                         \
        upk(add2(zgo1, zgo2), zg, zo);                                        \
        float ag = fmaf(-2.f, rcpf(ex2f(zg) + 1.f), 1.f);                     \
        float ao = rcpf(1.f + ex2f(zo));                                      \
        _Pragma("unroll")                                                     \
        for (int j = 0; j < 16; j++) {                                        \
            ulonglong2 vv = hv[j];                                            \
            zif1 = ffma2(vv.x, rkif[2 * j],     zif1);                        \
            zif2 = ffma2(vv.y, rkif[2 * j + 1], zif2);                        \
        }                                                                     \
        float zi, zf;                                                         \
        upk(add2(zif1, zif2), zi, zf);                                        \
        float ai = rcpf(1.f + ex2f(zi));                                      \
        float af = rcpf(1.f + ex2f(zf));                                      \
        c = fmaf(af, c, ai * ag);                                             \
        float h = ao * fmaf(-2.f, rcpf(ex2f(2.f * LOG2E * c) + 1.f), 1.f);    \
        hb[(TT) * 32 + lane] = h;                                             \
        h2[((TT) & 1) ^ 1][lane] = pk(h, h);                                  \
        __syncwarp();                                                         \
    }

    for (int t = 0; t < T_; t += 4) {
        LSTM_STEP(xq0, t);
        LSTM_STEP(xq1, t + 1);
        LSTM_STEP(xq2, t + 2);
        LSTM_STEP(xq3, t + 3);
    }
#undef LSTM_STEP
}

// ============================================================
// Kernel 4: attention partials. grid (8, 64): tile(4) x chunk(2) x b.
// 1 query row per thread (low regs -> 2 blocks/SM = 16 warps).
// Each block: rows [tile*256, +256) x s in [cid*512, +512).
// ht pre-scaled by log2e -> p = ex2(dot). Partial Z/acc to gmem.
// ============================================================
#define ATTN_SMEM (512 * 32 * 4)
__global__ __launch_bounds__(256, 2) void attn_kernel() {
    extern __shared__ float hs[];
    int tile = blockIdx.x >> 1, cid = blockIdx.x & 1;
    int b = blockIdx.y;
    int tid = threadIdx.x;
    const float* hbase = g_h + b * (T_ * 32);
    {   // stage this chunk's 512 keys
        const float4* src = (const float4*)(hbase + cid * 512 * 32);
        float4* dst = (float4*)hs;
        for (int i = tid; i < 4096; i += 256) dst[i] = src[i];
    }
    int r = tile * 256 + tid;
    ull ht[16];
    {
        const float4* hr = (const float4*)(hbase + r * 32);
#pragma unroll
        for (int j = 0; j < 8; j++) {
            float4 a = hr[j];
            ht[2 * j]     = pk(a.x * LOG2E, a.y * LOG2E);
            ht[2 * j + 1] = pk(a.z * LOG2E, a.w * LOG2E);
        }
    }
    __syncthreads();
    const ull z64 = pk(0.f, 0.f);
    ull acc[16];
#pragma unroll
    for (int k = 0; k < 16; k++) acc[k] = z64;
    float Z = 0.f;

    for (int s = 0; s < 512; s++) {
        const ulonglong2* hv = (const ulonglong2*)(hs + s * 32);  // uniform -> broadcast
        ull hp[16];
#pragma unroll
        for (int j = 0; j < 8; j++) {
            ulonglong2 v = hv[j];
            hp[2 * j] = v.x; hp[2 * j + 1] = v.y;
        }
        ull d1 = ffma2(hp[0], ht[0], z64);
        ull d2 = ffma2(hp[1], ht[1], z64);
#pragma unroll
        for (int k = 2; k < 16; k += 2) {
            d1 = ffma2(hp[k],     ht[k],     d1);
            d2 = ffma2(hp[k + 1], ht[k + 1], d2);
        }
        float a, bb;
        upk(add2(d1, d2), a, bb);
        float p = ex2f(a + bb);            // dot pre-scaled by log2e
        Z += p;
        ull pp = pk(p, p);
#pragma unroll
        for (int k = 0; k < 16; k++) acc[k] = ffma2(pp, hp[k], acc[k]);
    }
    int orow = (b * 2 + cid) * T_ + r;
    g_pz[orow] = Z;
    float4* po = (float4*)(g_pacc + (size_t)orow * 32);
#pragma unroll
    for (int k = 0; k < 8; k++) {
        float x0, y0, x1, y1;
        upk(acc[2 * k],     x0, y0);
        upk(acc[2 * k + 1], x1, y1);
        po[k] = make_float4(x0, y0, x1, y1);
    }
}

// ============================================================
// Kernel 5: combine partials -> ctx -> y = ctx^T h -> MLP -> out. grid 64.
// ============================================================
__global__ __launch_bounds__(256) void combine_final(const float* __restrict__ W1,
                                                     const float* __restrict__ b1,
                                                     const float* __restrict__ W2,
                                                     const float* __restrict__ b2,
                                                     float* __restrict__ out) {
    __shared__ float sctx[128 * 36];   // padded stride 36 (16B-aligned rows)
    __shared__ float sh[128 * 32];
    int b = blockIdx.x, tid = threadIdx.x;
    int dd = tid >> 3, ee = (tid & 7) * 4;
    float4 y4 = make_float4(0.f, 0.f, 0.f, 0.f);
    const float* pz0 = g_pz + (b * 2) * T_;
    const float* pz1 = g_pz + (b * 2 + 1) * T_;

    for (int tb = 0; tb < 8; tb++) {
        {   // stage ctx: 2 threads per t (halves of 16 dims)
            int t = tb * 128 + (tid >> 1);
            int half = (tid & 1) * 16;
            float inv = 1.f / (pz0[t] + pz1[t]);
            const float4* pa0 = (const float4*)(g_pacc + ((size_t)(b * 2) * T_ + t) * 32 + half);
            const float4* pa1 = (const float4*)(g_pacc + ((size_t)(b * 2 + 1) * T_ + t) * 32 + half);
            float4* so = (float4*)(sctx + (tid >> 1) * 36 + half);
#pragma unroll
            for (int q = 0; q < 4; q++) {
                float4 u = pa0[q], v = pa1[q];
                so[q] = make_float4((u.x + v.x) * inv, (u.y + v.y) * inv,
                                    (u.z + v.z) * inv, (u.w + v.w) * inv);
            }
        }
        {   // stage h tile
            const float4* hsrc = (const float4*)(g_h + b * (T_ * 32) + tb * 128 * 32);
            float4* hdst = (float4*)sh;
#pragma unroll
            for (int q = 0; q < 4; q++) hdst[tid + 256 * q] = hsrc[tid + 256 * q];
        }
        __syncthreads();
        for (int t2 = 0; t2 < 128; t2++) {
            float cv = sctx[t2 * 36 + dd];
            float4 hv = *(const float4*)(sh + t2 * 32 + ee);
            y4.x = fmaf(cv, hv.x, y4.x);
            y4.y = fmaf(cv, hv.y, y4.y);
            y4.z = fmaf(cv, hv.z, y4.z);
            y4.w = fmaf(cv, hv.w, y4.w);
        }
        __syncthreads();
    }
    // y -> smem (reuse sctx as flat [32][32])
    float* ysh = sctx;
    *(float4*)(ysh + dd * 32 + ee) = y4;
    __syncthreads();
    if (tid < 32) {
        int d = tid;
        float acc = b2[0];
        for (int e = 0; e < 32; e++) {
            float s = b1[e];
#pragma unroll
            for (int kk = 0; kk < 32; kk++)
                s = fmaf(ysh[d * 32 + kk], W1[kk * 32 + e], s);
            s = fmaxf(s, 0.f);
            acc = fmaf(s, W2[e], acc);
        }
        out[b * 32 + d] = 1.0f / (1.0f + __expf(-acc));
    }
}

// ============================================================
extern "C" void kernel_launch(void* const* d_in, const int* in_sizes, int n_in,
                              void* d_out, int out_size) {
    const int*   inputs = (const int*)  d_in[0];
    const float* emb    = (const float*)d_in[1];
    const float* klstm  = (const float*)d_in[2];
    const float* rklstm = (const float*)d_in[3];
    const float* blstm  = (const float*)d_in[4];
    const float* W1     = (const float*)d_in[5];
    const float* b1     = (const float*)d_in[6];
    const float* W2     = (const float*)d_in[7];
    const float* b2     = (const float*)d_in[8];
    float* out = (float*)d_out;

    cudaFuncSetAttribute(attn_kernel, cudaFuncAttributeMaxDynamicSharedMemorySize,
                         ATTN_SMEM);

    queue_kernel<<<1, 1024>>>(inputs, out, out_size);
    xg_kernel<<<512, 256>>>(inputs, emb, klstm, blstm);
    lstm_kernel<<<64, 32>>>(rklstm);
    attn_kernel<<<dim3(8, 64), 256, ATTN_SMEM>>>();
    combine_final<<<64, 256>>>(W1, b1, W2, b2, out);
}

// round 9
// speedup vs baseline: 1.2694x; 1.0740x over previous
#include <cuda_runtime.h>
#include <cuda_bf16.h>
#include <math.h>

#define B_  64
#define T_  1024
#define VOCAB_ 10000

typedef unsigned long long ull;

// ---- static scratch (no allocations allowed) ----
__device__ ulonglong2 g_xg2[B_ * T_ * 32];   // 33.5 MB : packed (i,f),(g,o), pre-scaled by log2e
__device__ float g_h [B_ * T_ * 32];         //  8.4 MB : LSTM hidden states
__device__ float g_pacc[B_ * 2 * T_ * 32];   // 16.8 MB : unnormalized ctx partials per s-chunk
__device__ float g_pz [B_ * 2 * T_];         //  0.5 MB : partial softmax sums per s-chunk

#define LOG2E 1.4426950408889634f

// ---- helpers ----
__device__ __forceinline__ float ex2f(float x) {
    float r; asm("ex2.approx.f32 %0, %1;" : "=f"(r) : "f"(x)); return r;
}
__device__ __forceinline__ float rcpf(float x) {
    float r; asm("rcp.approx.f32 %0, %1;" : "=f"(r) : "f"(x)); return r;
}
__device__ __forceinline__ ull pk(float a, float b) {
    ull r; asm("mov.b64 %0, {%1, %2};" : "=l"(r) : "f"(a), "f"(b)); return r;
}
__device__ __forceinline__ void upk(ull v, float& a, float& b) {
    asm("mov.b64 {%0, %1}, %2;" : "=f"(a), "=f"(b) : "l"(v));
}
__device__ __forceinline__ ull ffma2(ull a, ull b, ull c) {
    ull r; asm("fma.rn.f32x2 %0, %1, %2, %3;" : "=l"(r) : "l"(a), "l"(b), "l"(c)); return r;
}
__device__ __forceinline__ ull add2(ull a, ull b) {
    ull r; asm("add.rn.f32x2 %0, %1, %2;" : "=l"(r) : "l"(a), "l"(b)); return r;
}

// ============================================================
// Kernel 1: zero-token index queue (last 100 zeros, ascending, -1 padded front)
// ============================================================
__global__ void queue_kernel(const int* __restrict__ in, float* __restrict__ out,
                             int out_size) {
    if (out_size < 2248) return;
    float* q = out + (out_size - 200);
    int tid = threadIdx.x;                 // 0..1023
    int base = tid * 64;
    ull m = 0;
    const int4* p4 = (const int4*)(in + base);
#pragma unroll
    for (int k = 0; k < 16; k++) {
        int4 v = p4[k];
        if (v.x == 0 || v.x >= VOCAB_) m |= 1ull << (4 * k + 0);
        if (v.y == 0 || v.y >= VOCAB_) m |= 1ull << (4 * k + 1);
        if (v.z == 0 || v.z >= VOCAB_) m |= 1ull << (4 * k + 2);
        if (v.w == 0 || v.w >= VOCAB_) m |= 1ull << (4 * k + 3);
    }
    int cnt = __popcll(m);
    int lane = tid & 31, wid = tid >> 5;
    int v = cnt;
#pragma unroll
    for (int o = 1; o < 32; o <<= 1) {
        int t = __shfl_up_sync(0xffffffffu, v, o);
        if (lane >= o) v += t;
    }
    __shared__ int wsum[32];
    __shared__ int woff[32];
    __shared__ int stot;
    if (lane == 31) wsum[wid] = v;
    __syncthreads();
    if (wid == 0) {
        int x = wsum[lane];
        int y = x;
#pragma unroll
        for (int o = 1; o < 32; o <<= 1) {
            int t = __shfl_up_sync(0xffffffffu, y, o);
            if (lane >= o) y += t;
        }
        woff[lane] = y - x;
        if (lane == 31) stot = y;
    }
    __syncthreads();
    int total = stot;
    int excl = woff[wid] + v - cnt;
    if (tid < 200) q[tid] = -1.0f;
    __syncthreads();
    int r = excl;
    ull mm = m;
    while (mm) {
        int k = __ffsll(mm) - 1;
        mm &= mm - 1;
        int slot = r - total + 100;
        if (slot >= 0) {
            int p = base + k;
            q[slot * 2]     = (float)(p >> 10);
            q[slot * 2 + 1] = (float)(p & 1023);
        }
        r++;
    }
}

// ============================================================
// Kernel 2: xg = b_lstm + emb[id]@k, packed (i,f),(g,o), PRE-SCALED:
// i,f,o gates by -log2e (sigmoid via ex2), g gate by 2*log2e (tanh via ex2).
// ============================================================
__global__ __launch_bounds__(256) void xg_kernel(const int* __restrict__ inp,
                                                 const float* __restrict__ emb,
                                                 const float* __restrict__ klstm,
                                                 const float* __restrict__ blstm) {
    int b  = blockIdx.x >> 3;
    int tb = (blockIdx.x & 7) * 128;
    int tid = threadIdx.x, lane = tid & 31, w = tid >> 5;
    float kr[4][32];
#pragma unroll
    for (int d = 0; d < 32; d++)
#pragma unroll
        for (int qq = 0; qq < 4; qq++) kr[qq][d] = klstm[d * 128 + qq * 32 + lane];
    float br[4];
#pragma unroll
    for (int qq = 0; qq < 4; qq++) br[qq] = blstm[qq * 32 + lane];

    for (int i = 0; i < 16; i++) {
        int t = tb + w * 16 + i;
        int u = inp[b * T_ + t];
        int id = (u < VOCAB_) ? u : 0;
        float ev = emb[id * 32 + lane];
        float a0 = br[0], a1 = br[1], a2 = br[2], a3 = br[3];
#pragma unroll
        for (int d = 0; d < 32; d++) {
            float e = __shfl_sync(0xffffffffu, ev, d);
            a0 = fmaf(e, kr[0][d], a0);
            a1 = fmaf(e, kr[1][d], a1);
            a2 = fmaf(e, kr[2][d], a2);
            a3 = fmaf(e, kr[3][d], a3);
        }
        ulonglong2 vv;
        vv.x = pk(a0 * (-LOG2E), a1 * (-LOG2E));   // (i, f)  scaled for ex2-sigmoid
        vv.y = pk(a2 * (2.0f * LOG2E), a3 * (-LOG2E)); // (g, o)
        g_xg2[(b * T_ + t) * 32 + lane] = vv;
    }
}

// ============================================================
// Kernel 3: LSTM recurrence. 64 blocks x 1 warp. Thread = unit.
// 4 accumulator chains per gate-pair (depth 8). (g,o) matvec first so its
// MUFUs overlap (i,f) issue. c kept pre-scaled by 2*log2e (folded into ag).
// ============================================================
__global__ __launch_bounds__(32, 1) void lstm_kernel(const float* __restrict__ rk) {
    int b = blockIdx.x;
    int lane = threadIdx.x;
    ull rkif[32], rkgo[32];
#pragma unroll
    for (int d = 0; d < 32; d++) {
        const float* rr = rk + d * 128;
        rkif[d] = pk(rr[lane] * (-LOG2E),      rr[32 + lane] * (-LOG2E));
        rkgo[d] = pk(rr[64 + lane] * (2.0f * LOG2E), rr[96 + lane] * (-LOG2E));
    }
    __shared__ ull h2[2][32];
    h2[0][lane] = pk(0.f, 0.f);
    float c2 = 0.f;                          // c pre-scaled by 2*log2e
    float* hb = g_h + b * T_ * 32;
    const ulonglong2* xgb = g_xg2 + b * T_ * 32;
    ulonglong2 xq0 = xgb[lane];
    ulonglong2 xq1 = xgb[32 + lane];
    ulonglong2 xq2 = xgb[64 + lane];
    ulonglong2 xq3 = xgb[96 + lane];
    __syncwarp();
    const ull z64 = pk(0.f, 0.f);
    const float FOUR_L = 4.0f * LOG2E, TWO_L = 2.0f * LOG2E;

#define LSTM_STEP(XQ, TT)                                                     \
    {                                                                         \
        ull ga = (XQ).y, gb = z64, gc = z64, gd = z64;                        \
        ull ia = (XQ).x, ib = z64, ic = z64, id_ = z64;                       \
        if ((TT) + 4 < T_) (XQ) = xgb[((TT) + 4) * 32 + lane];                \
        const ulonglong2* hv = (const ulonglong2*)h2[(TT) & 1];               \
        _Pragma("unroll")                                                     \
        for (int j = 0; j < 8; j++) {                                         \
            ulonglong2 va = hv[2 * j], vb = hv[2 * j + 1];                    \
            ga = ffma2(va.x, rkgo[4 * j],     ga);                            \
            gb = ffma2(va.y, rkgo[4 * j + 1], gb);                            \
            gc = ffma2(vb.x, rkgo[4 * j + 2], gc);                            \
            gd = ffma2(vb.y, rkgo[4 * j + 3], gd);                            \
        }                                                                     \
        float zg, zo;                                                         \
        upk(add2(add2(ga, gb), add2(gc, gd)), zg, zo);                        \
        float ag2 = fmaf(-FOUR_L, rcpf(ex2f(zg) + 1.f), TWO_L);               \
        float ao  = rcpf(1.f + ex2f(zo));                                     \
        _Pragma("unroll")                                                     \
        for (int j = 0; j < 8; j++) {                                         \
            ulonglong2 va = hv[2 * j], vb = hv[2 * j + 1];                    \
            ia  = ffma2(va.x, rkif[4 * j],     ia);                           \
            ib  = ffma2(va.y, rkif[4 * j + 1], ib);                           \
            ic  = ffma2(vb.x, rkif[4 * j + 2], ic);                           \
            id_ = ffma2(vb.y, rkif[4 * j + 3], id_);                          \
        }                                                                     \
        float zi, zf;                                                         \
        upk(add2(add2(ia, ib), add2(ic, id_)), zi, zf);                       \
        float ai = rcpf(1.f + ex2f(zi));                                      \
        float af = rcpf(1.f + ex2f(zf));                                      \
        c2 = fmaf(af, c2, ai * ag2);                                          \
        float h = ao * fmaf(-2.f, rcpf(ex2f(c2) + 1.f), 1.f);                 \
        hb[(TT) * 32 + lane] = h;                                             \
        h2[((TT) & 1) ^ 1][lane] = pk(h, h);                                  \
        __syncwarp();                                                         \
    }

    for (int t = 0; t < T_; t += 4) {
        LSTM_STEP(xq0, t);
        LSTM_STEP(xq1, t + 1);
        LSTM_STEP(xq2, t + 2);
        LSTM_STEP(xq3, t + 3);
    }
#undef LSTM_STEP
}

// ============================================================
// Kernel 4: attention partials. grid (8, 64): tile(4) x chunk(2) x b.
// 1 query row per thread. Software-pipelined key loads: hi-half loaded at
// iter top, next-iter lo-half prefetched before the acc FMAs.
// ht pre-scaled by log2e -> p = ex2(dot). Partial Z/acc to gmem.
// ============================================================
#define ATTN_SMEM (512 * 32 * 4)
__global__ __launch_bounds__(256, 2) void attn_kernel() {
    extern __shared__ float hs[];
    int tile = blockIdx.x >> 1, cid = blockIdx.x & 1;
    int b = blockIdx.y;
    int tid = threadIdx.x;
    const float* hbase = g_h + b * (T_ * 32);
    {   // stage this chunk's 512 keys
        const float4* src = (const float4*)(hbase + cid * 512 * 32);
        float4* dst = (float4*)hs;
        for (int i = tid; i < 4096; i += 256) dst[i] = src[i];
    }
    int r = tile * 256 + tid;
    ull ht[16];
    {
        const float4* hr = (const float4*)(hbase + r * 32);
#pragma unroll
        for (int j = 0; j < 8; j++) {
            float4 a = hr[j];
            ht[2 * j]     = pk(a.x * LOG2E, a.y * LOG2E);
            ht[2 * j + 1] = pk(a.z * LOG2E, a.w * LOG2E);
        }
    }
    __syncthreads();
    const ull z64 = pk(0.f, 0.f);
    ull acc[16];
#pragma unroll
    for (int k = 0; k < 16; k++) acc[k] = z64;
    float Z = 0.f;

    ull hp[16];
    {   // preload lo-half (dims 0..15) of s=0
        const ulonglong2* h0 = (const ulonglong2*)hs;
        ulonglong2 a0 = h0[0], a1 = h0[1], a2 = h0[2], a3 = h0[3];
        hp[0] = a0.x; hp[1] = a0.y; hp[2] = a1.x; hp[3] = a1.y;
        hp[4] = a2.x; hp[5] = a2.y; hp[6] = a3.x; hp[7] = a3.y;
    }

    for (int s = 0; s < 512; s++) {
        const ulonglong2* hv = (const ulonglong2*)(hs + s * 32);
        // hi half (dims 16..31) for current s
        ulonglong2 b0 = hv[4], b1 = hv[5], b2 = hv[6], b3 = hv[7];
        hp[8]  = b0.x; hp[9]  = b0.y; hp[10] = b1.x; hp[11] = b1.y;
        hp[12] = b2.x; hp[13] = b2.y; hp[14] = b3.x; hp[15] = b3.y;
        // dot
        ull d1 = ffma2(hp[0], ht[0], z64);
        ull d2 = ffma2(hp[1], ht[1], z64);
#pragma unroll
        for (int k = 2; k < 16; k += 2) {
            d1 = ffma2(hp[k],     ht[k],     d1);
            d2 = ffma2(hp[k + 1], ht[k + 1], d2);
        }
        float a, bb;
        upk(add2(d1, d2), a, bb);
        float p = ex2f(a + bb);            // dot pre-scaled by log2e
        // prefetch lo-half of next s before the acc FMAs (covers LDS latency)
        const ulonglong2* hn = (const ulonglong2*)(hs + ((s + 1) & 511) * 32);
        ulonglong2 n0 = hn[0], n1 = hn[1], n2 = hn[2], n3 = hn[3];
        Z += p;
        ull pp = pk(p, p);
#pragma unroll
        for (int k = 0; k < 16; k++) acc[k] = ffma2(pp, hp[k], acc[k]);
        hp[0] = n0.x; hp[1] = n0.y; hp[2] = n1.x; hp[3] = n1.y;
        hp[4] = n2.x; hp[5] = n2.y; hp[6] = n3.x; hp[7] = n3.y;
    }
    int orow = (b * 2 + cid) * T_ + r;
    g_pz[orow] = Z;
    float4* po = (float4*)(g_pacc + (size_t)orow * 32);
#pragma unroll
    for (int k = 0; k < 8; k++) {
        float x0, y0, x1, y1;
        upk(acc[2 * k],     x0, y0);
        upk(acc[2 * k + 1], x1, y1);
        po[k] = make_float4(x0, y0, x1, y1);
    }
}

// ============================================================
// Kernel 5: combine partials -> ctx -> y = ctx^T h -> MLP -> out. grid 64.
// ============================================================
__global__ __launch_bounds__(256) void combine_final(const float* __restrict__ W1,
                                                     const float* __restrict__ b1,
                                                     const float* __restrict__ W2,
                                                     const float* __restrict__ b2,
                                                     float* __restrict__ out) {
    __shared__ float sctx[128 * 36];   // padded stride 36 (16B-aligned rows)
    __shared__ float sh[128 * 32];
    int b = blockIdx.x, tid = threadIdx.x;
    int dd = tid >> 3, ee = (tid & 7) * 4;
    float4 y4 = make_float4(0.f, 0.f, 0.f, 0.f);
    const float* pz0 = g_pz + (b * 2) * T_;
    const float* pz1 = g_pz + (b * 2 + 1) * T_;

    for (int tb = 0; tb < 8; tb++) {
        {   // stage ctx: 2 threads per t (halves of 16 dims)
            int t = tb * 128 + (tid >> 1);
            int half = (tid & 1) * 16;
            float inv = 1.f / (pz0[t] + pz1[t]);
            const float4* pa0 = (const float4*)(g_pacc + ((size_t)(b * 2) * T_ + t) * 32 + half);
            const float4* pa1 = (const float4*)(g_pacc + ((size_t)(b * 2 + 1) * T_ + t) * 32 + half);
            float4* so = (float4*)(sctx + (tid >> 1) * 36 + half);
#pragma unroll
            for (int q = 0; q < 4; q++) {
                float4 u = pa0[q], v = pa1[q];
                so[q] = make_float4((u.x + v.x) * inv, (u.y + v.y) * inv,
                                    (u.z + v.z) * inv, (u.w + v.w) * inv);
            }
        }
        {   // stage h tile
            const float4* hsrc = (const float4*)(g_h + b * (T_ * 32) + tb * 128 * 32);
            float4* hdst = (float4*)sh;
#pragma unroll
            for (int q = 0; q < 4; q++) hdst[tid + 256 * q] = hsrc[tid + 256 * q];
        }
        __syncthreads();
        for (int t2 = 0; t2 < 128; t2++) {
            float cv = sctx[t2 * 36 + dd];
            float4 hv = *(const float4*)(sh + t2 * 32 + ee);
            y4.x = fmaf(cv, hv.x, y4.x);
            y4.y = fmaf(cv, hv.y, y4.y);
            y4.z = fmaf(cv, hv.z, y4.z);
            y4.w = fmaf(cv, hv.w, y4.w);
        }
        __syncthreads();
    }
    // y -> smem (reuse sctx as flat [32][32])
    float* ysh = sctx;
    *(float4*)(ysh + dd * 32 + ee) = y4;
    __syncthreads();
    if (tid < 32) {
        int d = tid;
        float acc = b2[0];
        for (int e = 0; e < 32; e++) {
            float s = b1[e];
#pragma unroll
            for (int kk = 0; kk < 32; kk++)
                s = fmaf(ysh[d * 32 + kk], W1[kk * 32 + e], s);
            s = fmaxf(s, 0.f);
            acc = fmaf(s, W2[e], acc);
        }
        out[b * 32 + d] = 1.0f / (1.0f + __expf(-acc));
    }
}

// ============================================================
extern "C" void kernel_launch(void* const* d_in, const int* in_sizes, int n_in,
                              void* d_out, int out_size) {
    const int*   inputs = (const int*)  d_in[0];
    const float* emb    = (const float*)d_in[1];
    const float* klstm  = (const float*)d_in[2];
    const float* rklstm = (const float*)d_in[3];
    const float* blstm  = (const float*)d_in[4];
    const float* W1     = (const float*)d_in[5];
    const float* b1     = (const float*)d_in[6];
    const float* W2     = (const float*)d_in[7];
    const float* b2     = (const float*)d_in[8];
    float* out = (float*)d_out;

    cudaFuncSetAttribute(attn_kernel, cudaFuncAttributeMaxDynamicSharedMemorySize,
                         ATTN_SMEM);

    queue_kernel<<<1, 1024>>>(inputs, out, out_size);
    xg_kernel<<<512, 256>>>(inputs, emb, klstm, blstm);
    lstm_kernel<<<64, 32>>>(rklstm);
    attn_kernel<<<dim3(8, 64), 256, ATTN_SMEM>>>();
    combine_final<<<64, 256>>>(W1, b1, W2, b2, out);
}

// round 11
// speedup vs baseline: 1.3538x; 1.0665x over previous
#include <cuda_runtime.h>
#include <cuda_bf16.h>
#include <math.h>

#define B_  64
#define T_  1024
#define VOCAB_ 10000

typedef unsigned long long ull;

// ---- static scratch (no allocations allowed) ----
__device__ float g_xgf[B_ * T_ * 128];       // 33.5 MB : per-gate prescaled xg
__device__ float g_h [B_ * T_ * 32];         //  8.4 MB : LSTM hidden states
__device__ float g_pacc[B_ * 2 * T_ * 32];   // 16.8 MB : unnormalized ctx partials per s-chunk
__device__ float g_pz [B_ * 2 * T_];         //  0.5 MB : partial softmax sums per s-chunk

#define LOG2E 1.4426950408889634f

// ---- helpers ----
__device__ __forceinline__ float ex2f(float x) {
    float r; asm("ex2.approx.f32 %0, %1;" : "=f"(r) : "f"(x)); return r;
}
__device__ __forceinline__ float rcpf(float x) {
    float r; asm("rcp.approx.f32 %0, %1;" : "=f"(r) : "f"(x)); return r;
}
__device__ __forceinline__ ull pk(float a, float b) {
    ull r; asm("mov.b64 %0, {%1, %2};" : "=l"(r) : "f"(a), "f"(b)); return r;
}
__device__ __forceinline__ void upk(ull v, float& a, float& b) {
    asm("mov.b64 {%0, %1}, %2;" : "=f"(a), "=f"(b) : "l"(v));
}
__device__ __forceinline__ ull ffma2(ull a, ull b, ull c) {
    ull r; asm("fma.rn.f32x2 %0, %1, %2, %3;" : "=l"(r) : "l"(a), "l"(b), "l"(c)); return r;
}
__device__ __forceinline__ ull add2(ull a, ull b) {
    ull r; asm("add.rn.f32x2 %0, %1, %2;" : "=l"(r) : "l"(a), "l"(b)); return r;
}

// ============================================================
// Kernel 1: zero-token index queue (last 100 zeros, ascending, -1 padded front)
// ============================================================
__global__ void queue_kernel(const int* __restrict__ in, float* __restrict__ out,
                             int out_size) {
    if (out_size < 2248) return;
    float* q = out + (out_size - 200);
    int tid = threadIdx.x;                 // 0..1023
    int base = tid * 64;
    ull m = 0;
    const int4* p4 = (const int4*)(in + base);
#pragma unroll
    for (int k = 0; k < 16; k++) {
        int4 v = p4[k];
        if (v.x == 0 || v.x >= VOCAB_) m |= 1ull << (4 * k + 0);
        if (v.y == 0 || v.y >= VOCAB_) m |= 1ull << (4 * k + 1);
        if (v.z == 0 || v.z >= VOCAB_) m |= 1ull << (4 * k + 2);
        if (v.w == 0 || v.w >= VOCAB_) m |= 1ull << (4 * k + 3);
    }
    int cnt = __popcll(m);
    int lane = tid & 31, wid = tid >> 5;
    int v = cnt;
#pragma unroll
    for (int o = 1; o < 32; o <<= 1) {
        int t = __shfl_up_sync(0xffffffffu, v, o);
        if (lane >= o) v += t;
    }
    __shared__ int wsum[32];
    __shared__ int woff[32];
    __shared__ int stot;
    if (lane == 31) wsum[wid] = v;
    __syncthreads();
    if (wid == 0) {
        int x = wsum[lane];
        int y = x;
#pragma unroll
        for (int o = 1; o < 32; o <<= 1) {
            int t = __shfl_up_sync(0xffffffffu, y, o);
            if (lane >= o) y += t;
        }
        woff[lane] = y - x;
        if (lane == 31) stot = y;
    }
    __syncthreads();
    int total = stot;
    int excl = woff[wid] + v - cnt;
    if (tid < 200) q[tid] = -1.0f;
    __syncthreads();
    int r = excl;
    ull mm = m;
    while (mm) {
        int k = __ffsll(mm) - 1;
        mm &= mm - 1;
        int slot = r - total + 100;
        if (slot >= 0) {
            int p = base + k;
            q[slot * 2]     = (float)(p >> 10);
            q[slot * 2 + 1] = (float)(p & 1023);
        }
        r++;
    }
}

// ============================================================
// Kernel 2: xg = b_lstm + emb[id]@k, per-gate floats, PRE-SCALED:
// gates i,f,o by -log2e (sigmoid via ex2), gate g by 2*log2e (tanh via ex2).
// Layout: g_xgf[(b*T+t)*128 + gate*32 + unit]
// ============================================================
__global__ __launch_bounds__(256) void xg_kernel(const int* __restrict__ inp,
                                                 const float* __restrict__ emb,
                                                 const float* __restrict__ klstm,
                                                 const float* __restrict__ blstm) {
    int b  = blockIdx.x >> 3;
    int tb = (blockIdx.x & 7) * 128;
    int tid = threadIdx.x, lane = tid & 31, w = tid >> 5;
    float kr[4][32];
#pragma unroll
    for (int d = 0; d < 32; d++)
#pragma unroll
        for (int qq = 0; qq < 4; qq++) kr[qq][d] = klstm[d * 128 + qq * 32 + lane];
    float br[4];
#pragma unroll
    for (int qq = 0; qq < 4; qq++) br[qq] = blstm[qq * 32 + lane];

    for (int i = 0; i < 16; i++) {
        int t = tb + w * 16 + i;
        int u = inp[b * T_ + t];
        int id = (u < VOCAB_) ? u : 0;
        float ev = emb[id * 32 + lane];
        float a0 = br[0], a1 = br[1], a2 = br[2], a3 = br[3];
#pragma unroll
        for (int d = 0; d < 32; d++) {
            float e = __shfl_sync(0xffffffffu, ev, d);
            a0 = fmaf(e, kr[0][d], a0);
            a1 = fmaf(e, kr[1][d], a1);
            a2 = fmaf(e, kr[2][d], a2);
            a3 = fmaf(e, kr[3][d], a3);
        }
        float* o = g_xgf + (b * T_ + t) * 128;
        o[lane]      = a0 * (-LOG2E);        // i
        o[32 + lane] = a1 * (-LOG2E);        // f
        o[64 + lane] = a2 * (2.0f * LOG2E);  // g
        o[96 + lane] = a3 * (-LOG2E);        // o
    }
}

// ============================================================
// Kernel 3: LSTM recurrence. 64 blocks x 128 threads (one batch per block).
// Warp = gate (i,f,g,o), lane = unit. Per-warp matvec = 16 ffma2.
// Acts exchanged via smem; warp 0 owns the serial c/h tail.
// ============================================================
__global__ __launch_bounds__(128, 1) void lstm_kernel(const float* __restrict__ rk) {
    int b = blockIdx.x;
    int tid = threadIdx.x;
    int lane = tid & 31, w = tid >> 5;         // w = gate
    float scale = (w == 2) ? (2.0f * LOG2E) : (-LOG2E);
    ull rkp[16];
#pragma unroll
    for (int j = 0; j < 16; j++) {
        rkp[j] = pk(rk[(2 * j) * 128 + w * 32 + lane] * scale,
                    rk[(2 * j + 1) * 128 + w * 32 + lane] * scale);
    }
    __shared__ ull hsh[16];          // packed (h[2j], h[2j+1])
    __shared__ float acts[128];
    if (tid < 16) hsh[tid] = pk(0.f, 0.f);
    float c2 = 0.f;                  // c pre-scaled by 2*log2e
    float* hb = g_h + b * T_ * 32;
    const float* xgb = g_xgf + b * T_ * 128 + w * 32 + lane;
    float xq0 = xgb[0];
    float xq1 = xgb[128];
    float xq2 = xgb[256];
    float xq3 = xgb[384];
    __syncthreads();
    const float FOUR_L = 4.0f * LOG2E, TWO_L = 2.0f * LOG2E;
    const ull z64 = pk(0.f, 0.f);

#define LSTM_STEP(XQ, TT)                                                     \
    {                                                                         \
        ull za = pk(XQ, 0.f), zb = z64;                                       \
        if ((TT) + 4 < T_) XQ = xgb[((TT) + 4) * 128];                        \
        const ulonglong2* hv = (const ulonglong2*)hsh;                        \
        _Pragma("unroll")                                                     \
        for (int j = 0; j < 8; j++) {                                         \
            ulonglong2 vv = hv[j];                                            \
            za = ffma2(vv.x, rkp[2 * j],     za);                             \
            zb = ffma2(vv.y, rkp[2 * j + 1], zb);                             \
        }                                                                     \
        float zl, zh;                                                         \
        upk(add2(za, zb), zl, zh);                                            \
        float z = zl + zh;                                                    \
        float a;                                                              \
        if (w == 2) a = fmaf(-FOUR_L, rcpf(ex2f(z) + 1.f), TWO_L);            \
        else        a = rcpf(1.f + ex2f(z));                                  \
        acts[w * 32 + lane] = a;                                              \
        __syncthreads();                                                      \
        if (w == 0) {                                                         \
            float ai = a;                                                     \
            float af  = acts[32 + lane];                                      \
            float ag2 = acts[64 + lane];                                      \
            float ao  = acts[96 + lane];                                      \
            c2 = fmaf(af, c2, ai * ag2);                                      \
            float h = ao * fmaf(-2.f, rcpf(ex2f(c2) + 1.f), 1.f);             \
            hb[(TT) * 32 + lane] = h;                                         \
            int j2 = lane & 15;                                               \
            float he = __shfl_sync(0xffffffffu, h, 2 * j2);                   \
            float ho = __shfl_sync(0xffffffffu, h, 2 * j2 + 1);               \
            if (lane < 16) hsh[lane] = pk(he, ho);                            \
        }                                                                     \
        __syncthreads();                                                      \
    }

    for (int t = 0; t < T_; t += 4) {
        LSTM_STEP(xq0, t);
        LSTM_STEP(xq1, t + 1);
        LSTM_STEP(xq2, t + 2);
        LSTM_STEP(xq3, t + 3);
    }
#undef LSTM_STEP
}

// ============================================================
// Kernel 4: attention partials. grid (16, 64): row-tile(8) x chunk(2) x b.
// Block = 128 threads, 1 query row per thread, 3 blocks/SM (reg cap 168 -> no
// spills). Each block: rows [tile*128,+128) x s in [cid*512,+512).
// ht pre-scaled by log2e -> p = ex2(dot). Partial Z/acc to gmem.
// ============================================================
#define ATTN_SMEM (512 * 32 * 4)
__global__ __launch_bounds__(128, 3) void attn_kernel() {
    extern __shared__ float hs[];
    int tile = blockIdx.x >> 1, cid = blockIdx.x & 1;
    int b = blockIdx.y;
    int tid = threadIdx.x;
    const float* hbase = g_h + b * (T_ * 32);
    {   // stage this chunk's 512 keys (64KB)
        const float4* src = (const float4*)(hbase + cid * 512 * 32);
        float4* dst = (float4*)hs;
        for (int i = tid; i < 4096; i += 128) dst[i] = src[i];
    }
    int r = tile * 128 + tid;
    ull ht[16];
    {
        const float4* hr = (const float4*)(hbase + r * 32);
#pragma unroll
        for (int j = 0; j < 8; j++) {
            float4 a = hr[j];
            ht[2 * j]     = pk(a.x * LOG2E, a.y * LOG2E);
            ht[2 * j + 1] = pk(a.z * LOG2E, a.w * LOG2E);
        }
    }
    __syncthreads();
    const ull z64 = pk(0.f, 0.f);
    ull acc[16];
#pragma unroll
    for (int k = 0; k < 16; k++) acc[k] = z64;
    float Z = 0.f;

    for (int s = 0; s < 512; s++) {
        const ulonglong2* hv = (const ulonglong2*)(hs + s * 32);  // uniform -> broadcast
        ull hp[16];
#pragma unroll
        for (int j = 0; j < 8; j++) {
            ulonglong2 v = hv[j];
            hp[2 * j] = v.x; hp[2 * j + 1] = v.y;
        }
        ull d1 = ffma2(hp[0], ht[0], z64);
        ull d2 = ffma2(hp[1], ht[1], z64);
#pragma unroll
        for (int k = 2; k < 16; k += 2) {
            d1 = ffma2(hp[k],     ht[k],     d1);
            d2 = ffma2(hp[k + 1], ht[k + 1], d2);
        }
        float a, bb;
        upk(add2(d1, d2), a, bb);
        float p = ex2f(a + bb);            // dot pre-scaled by log2e
        Z += p;
        ull pp = pk(p, p);
#pragma unroll
        for (int k = 0; k < 16; k++) acc[k] = ffma2(pp, hp[k], acc[k]);
    }
    int orow = (b * 2 + cid) * T_ + r;
    g_pz[orow] = Z;
    float4* po = (float4*)(g_pacc + (size_t)orow * 32);
#pragma unroll
    for (int k = 0; k < 8; k++) {
        float x0, y0, x1, y1;
        upk(acc[2 * k],     x0, y0);
        upk(acc[2 * k + 1], x1, y1);
        po[k] = make_float4(x0, y0, x1, y1);
    }
}

// ============================================================
// Kernel 5: combine partials -> ctx -> y = ctx^T h -> MLP -> out. grid 64.
// ============================================================
__global__ __launch_bounds__(256) void combine_final(const float* __restrict__ W1,
                                                     const float* __restrict__ b1,
                                                     const float* __restrict__ W2,
                                                     const float* __restrict__ b2,
                                                     float* __restrict__ out) {
    __shared__ float sctx[128 * 36];   // padded stride 36 (16B-aligned rows)
    __shared__ float sh[128 * 32];
    int b = blockIdx.x, tid = threadIdx.x;
    int dd = tid >> 3, ee = (tid & 7) * 4;
    float4 y4 = make_float4(0.f, 0.f, 0.f, 0.f);
    const float* pz0 = g_pz + (b * 2) * T_;
    const float* pz1 = g_pz + (b * 2 + 1) * T_;

    for (int tb = 0; tb < 8; tb++) {
        {   // stage ctx: 2 threads per t (halves of 16 dims)
            int t = tb * 128 + (tid >> 1);
            int half = (tid & 1) * 16;
            float inv = 1.f / (pz0[t] + pz1[t]);
            const float4* pa0 = (const float4*)(g_pacc + ((size_t)(b * 2) * T_ + t) * 32 + half);
            const float4* pa1 = (const float4*)(g_pacc + ((size_t)(b * 2 + 1) * T_ + t) * 32 + half);
            float4* so = (float4*)(sctx + (tid >> 1) * 36 + half);
#pragma unroll
            for (int q = 0; q < 4; q++) {
                float4 u = pa0[q], v = pa1[q];
                so[q] = make_float4((u.x + v.x) * inv, (u.y + v.y) * inv,
                                    (u.z + v.z) * inv, (u.w + v.w) * inv);
            }
        }
        {   // stage h tile
            const float4* hsrc = (const float4*)(g_h + b * (T_ * 32) + tb * 128 * 32);
            float4* hdst = (float4*)sh;
#pragma unroll
            for (int q = 0; q < 4; q++) hdst[tid + 256 * q] = hsrc[tid + 256 * q];
        }
        __syncthreads();
        for (int t2 = 0; t2 < 128; t2++) {
            float cv = sctx[t2 * 36 + dd];
            float4 hv = *(const float4*)(sh + t2 * 32 + ee);
            y4.x = fmaf(cv, hv.x, y4.x);
            y4.y = fmaf(cv, hv.y, y4.y);
            y4.z = fmaf(cv, hv.z, y4.z);
            y4.w = fmaf(cv, hv.w, y4.w);
        }
        __syncthreads();
    }
    // y -> smem (reuse sctx as flat [32][32])
    float* ysh = sctx;
    *(float4*)(ysh + dd * 32 + ee) = y4;
    __syncthreads();
    if (tid < 32) {
        int d = tid;
        float acc = b2[0];
        for (int e = 0; e < 32; e++) {
            float s = b1[e];
#pragma unroll
            for (int kk = 0; kk < 32; kk++)
                s = fmaf(ysh[d * 32 + kk], W1[kk * 32 + e], s);
            s = fmaxf(s, 0.f);
            acc = fmaf(s, W2[e], acc);
        }
        out[b * 32 + d] = 1.0f / (1.0f + __expf(-acc));
    }
}

// ============================================================
extern "C" void kernel_launch(void* const* d_in, const int* in_sizes, int n_in,
                              void* d_out, int out_size) {
    const int*   inputs = (const int*)  d_in[0];
    const float* emb    = (const float*)d_in[1];
    const float* klstm  = (const float*)d_in[2];
    const float* rklstm = (const float*)d_in[3];
    const float* blstm  = (const float*)d_in[4];
    const float* W1     = (const float*)d_in[5];
    const float* b1     = (const float*)d_in[6];
    const float* W2     = (const float*)d_in[7];
    const float* b2     = (const float*)d_in[8];
    float* out = (float*)d_out;

    cudaFuncSetAttribute(attn_kernel, cudaFuncAttributeMaxDynamicSharedMemorySize,
                         ATTN_SMEM);

    queue_kernel<<<1, 1024>>>(inputs, out, out_size);
    xg_kernel<<<512, 256>>>(inputs, emb, klstm, blstm);
    lstm_kernel<<<64, 128>>>(rklstm);
    attn_kernel<<<dim3(16, 64), 128, ATTN_SMEM>>>();
    combine_final<<<64, 256>>>(W1, b1, W2, b2, out);
}